// round 1
// baseline (speedup 1.0000x reference)
#include <cuda_runtime.h>
#include <math.h>

// ---------------- problem constants ----------------
#define BB    32
#define TT    720
#define CC    862
#define MM    4
#define LTOK  866            // CC + MM
#define DMOD  512
#define HH    8
#define EH    64
#define FFD   2048
#define PRED  720
#define NROW  (BB * LTOK)    // 27712
#define LAYERS 3

// ---------------- device scratch (no allocs allowed) ----------------
__device__ float g_tok [BB * LTOK * TT];     // [B, L, T]
__device__ float g_x   [NROW * DMOD];
__device__ float g_q   [NROW * DMOD];
__device__ float g_k   [NROW * DMOD];
__device__ float g_v   [NROW * DMOD];
__device__ float g_a   [NROW * DMOD];
__device__ float g_tmp [NROW * DMOD];
__device__ float g_ff  [NROW * FFD];
__device__ float g_proj[NROW * PRED];
__device__ float g_mean[BB * CC];
__device__ float g_std [BB * CC];
__device__ float g_rstd[BB * CC];

// ---------------- RevIN stats ----------------
__global__ void revin_stats_kernel(const float* __restrict__ xe,
                                   float* __restrict__ mean,
                                   float* __restrict__ stdv,
                                   float* __restrict__ rstd) {
    int c = blockIdx.x * 128 + threadIdx.x;
    int b = blockIdx.y;
    if (c >= CC) return;
    const float* p = xe + (size_t)b * TT * CC + c;
    float s = 0.f, q = 0.f;
    for (int t = 0; t < TT; t++) {
        float v = p[(size_t)t * CC];
        s += v; q += v * v;
    }
    float mu  = s * (1.0f / TT);
    float var = q * (1.0f / TT) - mu * mu;
    float sd  = sqrtf(var + 1e-5f);
    int i = b * CC + c;
    mean[i] = mu; stdv[i] = sd; rstd[i] = 1.0f / sd;
}

// ---------------- tok = concat(norm(x_enc)^T, x_mark^T) ----------------
__global__ void build_tok_kernel(const float* __restrict__ xe,
                                 const float* __restrict__ xm,
                                 const float* __restrict__ mean,
                                 const float* __restrict__ rstd,
                                 const float* __restrict__ rw,
                                 const float* __restrict__ rb,
                                 float* __restrict__ tok) {
    int idx = blockIdx.x * blockDim.x + threadIdx.x;
    const int total = BB * LTOK * TT;
    if (idx >= total) return;
    int t = idx % TT;
    int l = (idx / TT) % LTOK;
    int b = idx / (TT * LTOK);
    float val;
    if (l < CC) {
        float xv = xe[((size_t)b * TT + t) * CC + l];
        int i = b * CC + l;
        val = (xv - mean[i]) * rstd[i] * rw[l] + rb[l];
    } else {
        val = xm[((size_t)b * TT + t) * MM + (l - CC)];
    }
    tok[idx] = val;
}

// ---------------- GEMM: C = act(A[N,K] @ W[K,Dout] + bias) ----------------
// 128x128 tile, BK=8, 8x8 per thread, 256 threads.
__global__ __launch_bounds__(256)
void gemm_kernel(const float* __restrict__ A, const float* __restrict__ W,
                 const float* __restrict__ bias, float* __restrict__ Cm,
                 int N, int K, int Dout, int act) {
    __shared__ float As[8][128];
    __shared__ float Bs[8][128];
    int tid  = threadIdx.x;
    int row0 = blockIdx.y * 128;
    int col0 = blockIdx.x * 128;
    int tx = tid & 15, ty = tid >> 4;
    int aRow = tid >> 1, aK = (tid & 1) << 2;
    int bRow = tid >> 5, bCol = (tid & 31) << 2;

    float acc[8][8];
#pragma unroll
    for (int i = 0; i < 8; i++)
#pragma unroll
        for (int j = 0; j < 8; j++) acc[i][j] = 0.f;

    const int  ar  = row0 + aRow;
    const bool aOk = (ar < N);
    const int  bc  = col0 + bCol;
    const bool bOk = (bc < Dout);   // Dout % 4 == 0 for all our Dout

    for (int k0 = 0; k0 < K; k0 += 8) {
        float4 av = make_float4(0.f, 0.f, 0.f, 0.f);
        float4 bv = make_float4(0.f, 0.f, 0.f, 0.f);
        if (aOk) av = *reinterpret_cast<const float4*>(A + (size_t)ar * K + k0 + aK);
        if (bOk) bv = *reinterpret_cast<const float4*>(W + (size_t)(k0 + bRow) * Dout + bc);
        __syncthreads();
        As[aK + 0][aRow] = av.x; As[aK + 1][aRow] = av.y;
        As[aK + 2][aRow] = av.z; As[aK + 3][aRow] = av.w;
        *reinterpret_cast<float4*>(&Bs[bRow][bCol]) = bv;
        __syncthreads();
#pragma unroll
        for (int kk = 0; kk < 8; kk++) {
            float af[8], bf[8];
            *reinterpret_cast<float4*>(af)     = *reinterpret_cast<const float4*>(&As[kk][ty * 8]);
            *reinterpret_cast<float4*>(af + 4) = *reinterpret_cast<const float4*>(&As[kk][ty * 8 + 4]);
            *reinterpret_cast<float4*>(bf)     = *reinterpret_cast<const float4*>(&Bs[kk][tx * 8]);
            *reinterpret_cast<float4*>(bf + 4) = *reinterpret_cast<const float4*>(&Bs[kk][tx * 8 + 4]);
#pragma unroll
            for (int i = 0; i < 8; i++)
#pragma unroll
                for (int j = 0; j < 8; j++) acc[i][j] += af[i] * bf[j];
        }
    }
#pragma unroll
    for (int i = 0; i < 8; i++) {
        int r = row0 + ty * 8 + i;
        if (r >= N) continue;
#pragma unroll
        for (int j = 0; j < 8; j++) {
            int cidx = col0 + tx * 8 + j;
            if (cidx >= Dout) continue;
            float vv = acc[i][j] + bias[cidx];
            if (act == 1)      vv = 1.0f / (1.0f + expf(-vv));
            else if (act == 2) vv = 0.5f * vv * (1.0f + erff(vv * 0.70710678118654752f));
            Cm[(size_t)r * Dout + cidx] = vv;
        }
    }
}

// ---------------- flow attention: one block per (b, h) ----------------
__global__ __launch_bounds__(256)
void attn_kernel(const float* __restrict__ q, const float* __restrict__ k,
                 const float* __restrict__ v, float* __restrict__ out) {
    int b = blockIdx.x >> 3, h = blockIdx.x & 7;
    const float* qp = q + ((size_t)b * LTOK) * DMOD + h * EH;
    const float* kp = k + ((size_t)b * LTOK) * DMOD + h * EH;
    const float* vp = v + ((size_t)b * LTOK) * DMOD + h * EH;
    float*       op = out + ((size_t)b * LTOK) * DMOD + h * EH;
    int tid = threadIdx.x, lane = tid & 31, wid = tid >> 5;
    const float eps = 1e-6f;

    __shared__ float s_nr[LTOK], s_nc[LTOK], s_nrref[LTOK], s_ncref[LTOK];
    __shared__ float s_ksum[EH], s_qsum[EH], s_kns[EH], s_qns[EH];
    __shared__ float s_kv[EH][EH];
    __shared__ float s_ck[8][EH], s_cv[8][EH];   // also used as partial-sum scratch
    __shared__ float s_red[8];

    // Phase A: column sums of q, k (post-sigmoid already)
    {
        int e = tid & 63, part = tid >> 6;
        float ka = 0.f, qa = 0.f;
        for (int s = part; s < LTOK; s += 4) {
            ka += kp[(size_t)s * DMOD + e];
            qa += qp[(size_t)s * DMOD + e];
        }
        s_ck[part][e] = ka;
        s_cv[part][e] = qa;
    }
    __syncthreads();
    if (tid < EH) {
        s_ksum[tid] = s_ck[0][tid] + s_ck[1][tid] + s_ck[2][tid] + s_ck[3][tid];
        s_qsum[tid] = s_cv[0][tid] + s_cv[1][tid] + s_cv[2][tid] + s_cv[3][tid];
    }
    __syncthreads();

    // Phase B: nr, nc (warp per row)
    for (int r = wid; r < LTOK; r += 8) {
        float qv0 = qp[(size_t)r * DMOD + lane], qv1 = qp[(size_t)r * DMOD + lane + 32];
        float kv0 = kp[(size_t)r * DMOD + lane], kv1 = kp[(size_t)r * DMOD + lane + 32];
        float dq = (qv0 + eps) * (s_ksum[lane] + eps) + (qv1 + eps) * (s_ksum[lane + 32] + eps);
        float dk = (kv0 + eps) * (s_qsum[lane] + eps) + (kv1 + eps) * (s_qsum[lane + 32] + eps);
        for (int o = 16; o; o >>= 1) {
            dq += __shfl_xor_sync(0xffffffffu, dq, o);
            dk += __shfl_xor_sync(0xffffffffu, dk, o);
        }
        if (lane == 0) { s_nr[r] = 1.0f / dq; s_nc[r] = 1.0f / dk; }
    }
    __syncthreads();

    // Phase C: weighted column sums k*nc, q*nr
    {
        int e = tid & 63, part = tid >> 6;
        float ka = 0.f, qa = 0.f;
        for (int s = part; s < LTOK; s += 4) {
            ka += kp[(size_t)s * DMOD + e] * s_nc[s];
            qa += qp[(size_t)s * DMOD + e] * s_nr[s];
        }
        s_ck[part][e] = ka;
        s_cv[part][e] = qa;
    }
    __syncthreads();
    if (tid < EH) {
        s_kns[tid] = s_ck[0][tid] + s_ck[1][tid] + s_ck[2][tid] + s_ck[3][tid];
        s_qns[tid] = s_cv[0][tid] + s_cv[1][tid] + s_cv[2][tid] + s_cv[3][tid];
    }
    __syncthreads();

    // Phase D: nr_ref (sigmoid), nc_ref logits
    for (int r = wid; r < LTOK; r += 8) {
        float qv0 = qp[(size_t)r * DMOD + lane], qv1 = qp[(size_t)r * DMOD + lane + 32];
        float kv0 = kp[(size_t)r * DMOD + lane], kv1 = kp[(size_t)r * DMOD + lane + 32];
        float dq = (qv0 + eps) * (s_kns[lane] + eps) + (qv1 + eps) * (s_kns[lane + 32] + eps);
        float dk = (kv0 + eps) * (s_qns[lane] + eps) + (kv1 + eps) * (s_qns[lane + 32] + eps);
        for (int o = 16; o; o >>= 1) {
            dq += __shfl_xor_sync(0xffffffffu, dq, o);
            dk += __shfl_xor_sync(0xffffffffu, dk, o);
        }
        if (lane == 0) {
            s_nrref[r] = 1.0f / (1.0f + expf(-dq));   // Lq/Ls == 1
            s_ncref[r] = dk;                           // softmax below
        }
    }
    __syncthreads();

    // Phase E: softmax over s_ncref, scaled by Ls
    float lmax = -1e30f;
    for (int s = tid; s < LTOK; s += 256) lmax = fmaxf(lmax, s_ncref[s]);
    for (int o = 16; o; o >>= 1) lmax = fmaxf(lmax, __shfl_xor_sync(0xffffffffu, lmax, o));
    if (lane == 0) s_red[wid] = lmax;
    __syncthreads();
    if (tid == 0) {
        float m = s_red[0];
        for (int i = 1; i < 8; i++) m = fmaxf(m, s_red[i]);
        s_red[0] = m;
    }
    __syncthreads();
    lmax = s_red[0];
    __syncthreads();
    float lsum = 0.f;
    for (int s = tid; s < LTOK; s += 256) {
        float ev = expf(s_ncref[s] - lmax);
        s_ncref[s] = ev;
        lsum += ev;
    }
    for (int o = 16; o; o >>= 1) lsum += __shfl_xor_sync(0xffffffffu, lsum, o);
    if (lane == 0) s_red[wid] = lsum;
    __syncthreads();
    if (tid == 0) {
        float m = 0.f;
        for (int i = 0; i < 8; i++) m += s_red[i];
        s_red[0] = m;
    }
    __syncthreads();
    float scl = (float)LTOK / s_red[0];
    __syncthreads();
    for (int s = tid; s < LTOK; s += 256) s_ncref[s] *= scl;
    __syncthreads();

    // Phase F: kv[e][d] = sum_s k[s,e] * v[s,d] * nc_ref[s]
    int e_own = tid >> 2;
    int d0    = (tid & 3) * 16;
    float acc[16];
#pragma unroll
    for (int i = 0; i < 16; i++) acc[i] = 0.f;
    for (int s0 = 0; s0 < LTOK; s0 += 8) {
        for (int i = tid; i < 512; i += 256) {
            int j = i >> 6, e = i & 63;
            int s = s0 + j;
            float kk = 0.f, vv = 0.f;
            if (s < LTOK) {
                kk = kp[(size_t)s * DMOD + e];
                vv = vp[(size_t)s * DMOD + e] * s_ncref[s];
            }
            s_ck[j][e] = kk;
            s_cv[j][e] = vv;
        }
        __syncthreads();
#pragma unroll
        for (int j = 0; j < 8; j++) {
            float ke = s_ck[j][e_own];
#pragma unroll
            for (int i = 0; i < 16; i++) acc[i] += ke * s_cv[j][d0 + i];
        }
        __syncthreads();
    }
#pragma unroll
    for (int i = 0; i < 16; i++) s_kv[e_own][d0 + i] = acc[i];
    __syncthreads();

    // Phase G: out[l,d] = (sum_e q[l,e] kv[e,d]) * nr[l] * nr_ref[l]
    for (int r = wid; r < LTOK; r += 8) {
        s_ck[wid][lane]      = qp[(size_t)r * DMOD + lane];
        s_ck[wid][lane + 32] = qp[(size_t)r * DMOD + lane + 32];
        __syncwarp();
        float a0 = 0.f, a1 = 0.f;
#pragma unroll
        for (int e = 0; e < EH; e++) {
            float qv = s_ck[wid][e];
            a0 += qv * s_kv[e][lane];
            a1 += qv * s_kv[e][lane + 32];
        }
        float sc = s_nr[r] * s_nrref[r];
        op[(size_t)r * DMOD + lane]      = a0 * sc;
        op[(size_t)r * DMOD + lane + 32] = a1 * sc;
        __syncwarp();
    }
}

// ---------------- residual add + LayerNorm (row per block, D=512) ----------------
__global__ __launch_bounds__(256)
void add_ln_kernel(float* __restrict__ x, const float* __restrict__ res,
                   const float* __restrict__ w, const float* __restrict__ bb,
                   int useRes) {
    __shared__ float s_s[8], s_q[8];
    int row = blockIdx.x, tid = threadIdx.x, lane = tid & 31, wid = tid >> 5;
    size_t base = (size_t)row * DMOD;
    float v0 = x[base + tid], v1 = x[base + tid + 256];
    if (useRes) { v0 += res[base + tid]; v1 += res[base + tid + 256]; }
    float s = v0 + v1, q = v0 * v0 + v1 * v1;
    for (int o = 16; o; o >>= 1) {
        s += __shfl_xor_sync(0xffffffffu, s, o);
        q += __shfl_xor_sync(0xffffffffu, q, o);
    }
    if (lane == 0) { s_s[wid] = s; s_q[wid] = q; }
    __syncthreads();
    if (tid == 0) {
        float ss = 0.f, qq = 0.f;
        for (int i = 0; i < 8; i++) { ss += s_s[i]; qq += s_q[i]; }
        s_s[0] = ss; s_q[0] = qq;
    }
    __syncthreads();
    float mu  = s_s[0] * (1.0f / DMOD);
    float var = s_q[0] * (1.0f / DMOD) - mu * mu;
    float r   = rsqrtf(var + 1e-5f);
    x[base + tid]       = (v0 - mu) * r * w[tid] + bb[tid];
    x[base + tid + 256] = (v1 - mu) * r * w[tid + 256] + bb[tid + 256];
}

// ---------------- output: transpose + RevIN denorm ----------------
__global__ void out_kernel(const float* __restrict__ proj,
                           const float* __restrict__ rw, const float* __restrict__ rb,
                           const float* __restrict__ mean, const float* __restrict__ stdv,
                           float* __restrict__ out) {
    int idx = blockIdx.x * blockDim.x + threadIdx.x;
    const int total = BB * PRED * CC;
    if (idx >= total) return;
    int c = idx % CC;
    int t = (idx / CC) % PRED;
    int b = idx / (CC * PRED);
    float p = proj[((size_t)b * LTOK + c) * PRED + t];
    float v = (p - rb[c]) / (rw[c] + 1e-10f);   // REVIN_EPS^2
    out[idx] = v * stdv[b * CC + c] + mean[b * CC + c];
}

// ---------------- host orchestration ----------------
static inline void launch_gemm(const float* A, const float* W, const float* bias,
                               float* Cm, int N, int K, int Dout, int act) {
    dim3 grid((Dout + 127) / 128, (N + 127) / 128);
    gemm_kernel<<<grid, 256>>>(A, W, bias, Cm, N, K, Dout, act);
}

extern "C" void kernel_launch(void* const* d_in, const int* in_sizes, int n_in,
                              void* d_out, int out_size) {
    const float* x_enc   = (const float*)d_in[0];
    const float* x_mark  = (const float*)d_in[1];
    const float* revin_w = (const float*)d_in[4];
    const float* revin_b = (const float*)d_in[5];
    const float* emb_W   = (const float*)d_in[6];
    const float* emb_b   = (const float*)d_in[7];
    const float* Wq = (const float*)d_in[8],  *bq = (const float*)d_in[9];
    const float* Wk = (const float*)d_in[10], *bk = (const float*)d_in[11];
    const float* Wv = (const float*)d_in[12], *bv = (const float*)d_in[13];
    const float* Wo = (const float*)d_in[14], *bo = (const float*)d_in[15];
    const float* ff1_W = (const float*)d_in[16], *ff1_b = (const float*)d_in[17];
    const float* ff2_W = (const float*)d_in[18], *ff2_b = (const float*)d_in[19];
    const float* ln1_w = (const float*)d_in[20], *ln1_b = (const float*)d_in[21];
    const float* ln2_w = (const float*)d_in[22], *ln2_b = (const float*)d_in[23];
    const float* lnf_w = (const float*)d_in[24], *lnf_b = (const float*)d_in[25];
    const float* proj_W = (const float*)d_in[26], *proj_b = (const float*)d_in[27];

    float *tok, *x, *q, *k, *v, *a, *tmp, *ff, *proj, *mean, *stdv, *rstd;
    cudaGetSymbolAddress((void**)&tok,  g_tok);
    cudaGetSymbolAddress((void**)&x,    g_x);
    cudaGetSymbolAddress((void**)&q,    g_q);
    cudaGetSymbolAddress((void**)&k,    g_k);
    cudaGetSymbolAddress((void**)&v,    g_v);
    cudaGetSymbolAddress((void**)&a,    g_a);
    cudaGetSymbolAddress((void**)&tmp,  g_tmp);
    cudaGetSymbolAddress((void**)&ff,   g_ff);
    cudaGetSymbolAddress((void**)&proj, g_proj);
    cudaGetSymbolAddress((void**)&mean, g_mean);
    cudaGetSymbolAddress((void**)&stdv, g_std);
    cudaGetSymbolAddress((void**)&rstd, g_rstd);

    // RevIN stats + token build
    revin_stats_kernel<<<dim3((CC + 127) / 128, BB), 128>>>(x_enc, mean, stdv, rstd);
    {
        int total = BB * LTOK * TT;
        build_tok_kernel<<<(total + 255) / 256, 256>>>(x_enc, x_mark, mean, rstd,
                                                       revin_w, revin_b, tok);
    }
    // embedding
    launch_gemm(tok, emb_W, emb_b, x, NROW, TT, DMOD, 0);

    for (int l = 0; l < LAYERS; l++) {
        const float* wq = Wq + (size_t)l * DMOD * DMOD;
        const float* wk = Wk + (size_t)l * DMOD * DMOD;
        const float* wv = Wv + (size_t)l * DMOD * DMOD;
        const float* wo = Wo + (size_t)l * DMOD * DMOD;
        launch_gemm(x, wq, bq + l * DMOD, q, NROW, DMOD, DMOD, 1);  // sigmoid(q)
        launch_gemm(x, wk, bk + l * DMOD, k, NROW, DMOD, DMOD, 1);  // sigmoid(k)
        launch_gemm(x, wv, bv + l * DMOD, v, NROW, DMOD, DMOD, 0);
        attn_kernel<<<BB * HH, 256>>>(q, k, v, a);
        launch_gemm(a, wo, bo + l * DMOD, tmp, NROW, DMOD, DMOD, 0);
        add_ln_kernel<<<NROW, 256>>>(x, tmp, ln1_w + l * DMOD, ln1_b + l * DMOD, 1);
        launch_gemm(x, ff1_W + (size_t)l * DMOD * FFD, ff1_b + l * FFD, ff,
                    NROW, DMOD, FFD, 2);                            // gelu
        launch_gemm(ff, ff2_W + (size_t)l * FFD * DMOD, ff2_b + l * DMOD, tmp,
                    NROW, FFD, DMOD, 0);
        add_ln_kernel<<<NROW, 256>>>(x, tmp, ln2_w + l * DMOD, ln2_b + l * DMOD, 1);
    }
    // final LN
    add_ln_kernel<<<NROW, 256>>>(x, nullptr, lnf_w, lnf_b, 0);
    // projection
    launch_gemm(x, proj_W, proj_b, proj, NROW, DMOD, PRED, 0);
    // output transpose + denorm
    {
        int total = BB * PRED * CC;
        out_kernel<<<(total + 255) / 256, 256>>>(proj, revin_w, revin_b, mean, stdv,
                                                 (float*)d_out);
    }
}

// round 2
// speedup vs baseline: 2.2800x; 2.2800x over previous
#include <cuda_runtime.h>
#include <math.h>
#include <stdint.h>

// ---------------- problem constants ----------------
#define BB    32
#define TT    720
#define CC    862
#define MM    4
#define LTOK  866            // CC + MM
#define DMOD  512
#define HH    8
#define EH    64
#define FFD   2048
#define PRED  720
#define NROW  (BB * LTOK)    // 27712
#define LAYERS 3

// ---------------- device scratch (no allocs allowed) ----------------
__device__ float g_tok [BB * LTOK * TT];     // [B, L, T]
__device__ float g_x   [NROW * DMOD];
__device__ float g_q   [NROW * DMOD];
__device__ float g_k   [NROW * DMOD];
__device__ float g_v   [NROW * DMOD];
__device__ float g_a   [NROW * DMOD];
__device__ float g_tmp [NROW * DMOD];
__device__ float g_ff  [NROW * FFD];
__device__ float g_proj[NROW * PRED];
__device__ float g_mean[BB * CC];
__device__ float g_std [BB * CC];
__device__ float g_rstd[BB * CC];

// ---------------- RevIN stats ----------------
__global__ void revin_stats_kernel(const float* __restrict__ xe,
                                   float* __restrict__ mean,
                                   float* __restrict__ stdv,
                                   float* __restrict__ rstd) {
    int c = blockIdx.x * 128 + threadIdx.x;
    int b = blockIdx.y;
    if (c >= CC) return;
    const float* p = xe + (size_t)b * TT * CC + c;
    float s = 0.f, q = 0.f;
    for (int t = 0; t < TT; t++) {
        float v = p[(size_t)t * CC];
        s += v; q += v * v;
    }
    float mu  = s * (1.0f / TT);
    float var = q * (1.0f / TT) - mu * mu;
    float sd  = sqrtf(var + 1e-5f);
    int i = b * CC + c;
    mean[i] = mu; stdv[i] = sd; rstd[i] = 1.0f / sd;
}

// ---------------- tok = concat(norm(x_enc)^T, x_mark^T) ----------------
__global__ void build_tok_kernel(const float* __restrict__ xe,
                                 const float* __restrict__ xm,
                                 const float* __restrict__ mean,
                                 const float* __restrict__ rstd,
                                 const float* __restrict__ rw,
                                 const float* __restrict__ rb,
                                 float* __restrict__ tok) {
    int idx = blockIdx.x * blockDim.x + threadIdx.x;
    const int total = BB * LTOK * TT;
    if (idx >= total) return;
    int t = idx % TT;
    int l = (idx / TT) % LTOK;
    int b = idx / (TT * LTOK);
    float val;
    if (l < CC) {
        float xv = xe[((size_t)b * TT + t) * CC + l];
        int i = b * CC + l;
        val = (xv - mean[i]) * rstd[i] * rw[l] + rb[l];
    } else {
        val = xm[((size_t)b * TT + t) * MM + (l - CC)];
    }
    tok[idx] = val;
}

// ---------------- TF32 tensor-core GEMM ----------------
// C = act(A[N,K] @ W[K,Dout] + bias). 128x128x16 block tile, 8 warps,
// each warp 64x32 via m16n8k8 tf32 mma. Double-buffered smem.
__device__ __forceinline__ uint32_t f2tf32(float x) {
    uint32_t r;
    asm("cvt.rna.tf32.f32 %0, %1;" : "=r"(r) : "f"(x));
    return r;
}

#define SPAD 136   // 128 + 8 pad (conflict-free fragment reads)

__global__ __launch_bounds__(256)
void gemm_tf32_kernel(const float* __restrict__ A, const float* __restrict__ W,
                      const float* __restrict__ bias, float* __restrict__ Cm,
                      int N, int K, int Dout, int act) {
    __shared__ uint32_t As[2][16][SPAD];   // [k][m]
    __shared__ uint32_t Bs[2][16][SPAD];   // [k][n]

    const int tid  = threadIdx.x;
    const int lane = tid & 31;
    const int wid  = tid >> 5;
    const int wRow = (wid & 1) * 64;      // 2 warps along M
    const int wCol = (wid >> 1) * 32;     // 4 warps along N
    const int gID  = lane >> 2;           // 0..7
    const int tg   = lane & 3;            // 0..3

    const int row0 = blockIdx.y * 128;
    const int col0 = blockIdx.x * 128;

    // global A load mapping: 2 x float4 per thread per tile
    const int aRow = tid >> 2;            // 0..63 (+64 chunk)
    const int aK   = (tid & 3) << 2;      // 0,4,8,12
    const int ar0  = min(row0 + aRow,      N - 1);
    const int ar1  = min(row0 + aRow + 64, N - 1);
    // global B load mapping: 2 x float4 per thread per tile
    const int bK   = tid >> 5;            // 0..7 (+8 chunk)
    const int bCol = (tid & 31) << 2;
    const int bc   = min(col0 + bCol, Dout - 4);

    float acc[4][4][4];
#pragma unroll
    for (int i = 0; i < 4; i++)
#pragma unroll
        for (int j = 0; j < 4; j++)
#pragma unroll
            for (int r = 0; r < 4; r++) acc[i][j][r] = 0.f;

    const int nIter = K >> 4;

    // prologue: tile 0
    float4 av0 = *reinterpret_cast<const float4*>(A + (size_t)ar0 * K + aK);
    float4 av1 = *reinterpret_cast<const float4*>(A + (size_t)ar1 * K + aK);
    float4 bv0 = *reinterpret_cast<const float4*>(W + (size_t)bK * Dout + bc);
    float4 bv1 = *reinterpret_cast<const float4*>(W + (size_t)(bK + 8) * Dout + bc);
    {
        As[0][aK + 0][aRow] = f2tf32(av0.x); As[0][aK + 1][aRow] = f2tf32(av0.y);
        As[0][aK + 2][aRow] = f2tf32(av0.z); As[0][aK + 3][aRow] = f2tf32(av0.w);
        As[0][aK + 0][aRow + 64] = f2tf32(av1.x); As[0][aK + 1][aRow + 64] = f2tf32(av1.y);
        As[0][aK + 2][aRow + 64] = f2tf32(av1.z); As[0][aK + 3][aRow + 64] = f2tf32(av1.w);
        Bs[0][bK][bCol + 0] = f2tf32(bv0.x); Bs[0][bK][bCol + 1] = f2tf32(bv0.y);
        Bs[0][bK][bCol + 2] = f2tf32(bv0.z); Bs[0][bK][bCol + 3] = f2tf32(bv0.w);
        Bs[0][bK + 8][bCol + 0] = f2tf32(bv1.x); Bs[0][bK + 8][bCol + 1] = f2tf32(bv1.y);
        Bs[0][bK + 8][bCol + 2] = f2tf32(bv1.z); Bs[0][bK + 8][bCol + 3] = f2tf32(bv1.w);
    }
    __syncthreads();

    int buf = 0;
    for (int t = 0; t < nIter; t++) {
        // issue next tile's global loads early
        if (t + 1 < nIter) {
            int k0 = (t + 1) << 4;
            av0 = *reinterpret_cast<const float4*>(A + (size_t)ar0 * K + k0 + aK);
            av1 = *reinterpret_cast<const float4*>(A + (size_t)ar1 * K + k0 + aK);
            bv0 = *reinterpret_cast<const float4*>(W + (size_t)(k0 + bK) * Dout + bc);
            bv1 = *reinterpret_cast<const float4*>(W + (size_t)(k0 + bK + 8) * Dout + bc);
        }
        // compute on current buffer
#pragma unroll
        for (int ks = 0; ks < 2; ks++) {
            const int kb = ks * 8;
            uint32_t af[4][4];
            uint32_t bf[4][2];
#pragma unroll
            for (int i = 0; i < 4; i++) {
                int r = wRow + i * 16 + gID;
                af[i][0] = As[buf][kb + tg][r];
                af[i][1] = As[buf][kb + tg][r + 8];
                af[i][2] = As[buf][kb + tg + 4][r];
                af[i][3] = As[buf][kb + tg + 4][r + 8];
            }
#pragma unroll
            for (int j = 0; j < 4; j++) {
                int c = wCol + j * 8 + gID;
                bf[j][0] = Bs[buf][kb + tg][c];
                bf[j][1] = Bs[buf][kb + tg + 4][c];
            }
#pragma unroll
            for (int i = 0; i < 4; i++)
#pragma unroll
                for (int j = 0; j < 4; j++) {
                    asm volatile(
                        "mma.sync.aligned.m16n8k8.row.col.f32.tf32.tf32.f32 "
                        "{%0,%1,%2,%3}, {%4,%5,%6,%7}, {%8,%9}, {%0,%1,%2,%3};"
                        : "+f"(acc[i][j][0]), "+f"(acc[i][j][1]),
                          "+f"(acc[i][j][2]), "+f"(acc[i][j][3])
                        : "r"(af[i][0]), "r"(af[i][1]), "r"(af[i][2]), "r"(af[i][3]),
                          "r"(bf[j][0]), "r"(bf[j][1]));
                }
        }
        // stage next tile
        if (t + 1 < nIter) {
            int nb = buf ^ 1;
            As[nb][aK + 0][aRow] = f2tf32(av0.x); As[nb][aK + 1][aRow] = f2tf32(av0.y);
            As[nb][aK + 2][aRow] = f2tf32(av0.z); As[nb][aK + 3][aRow] = f2tf32(av0.w);
            As[nb][aK + 0][aRow + 64] = f2tf32(av1.x); As[nb][aK + 1][aRow + 64] = f2tf32(av1.y);
            As[nb][aK + 2][aRow + 64] = f2tf32(av1.z); As[nb][aK + 3][aRow + 64] = f2tf32(av1.w);
            Bs[nb][bK][bCol + 0] = f2tf32(bv0.x); Bs[nb][bK][bCol + 1] = f2tf32(bv0.y);
            Bs[nb][bK][bCol + 2] = f2tf32(bv0.z); Bs[nb][bK][bCol + 3] = f2tf32(bv0.w);
            Bs[nb][bK + 8][bCol + 0] = f2tf32(bv1.x); Bs[nb][bK + 8][bCol + 1] = f2tf32(bv1.y);
            Bs[nb][bK + 8][bCol + 2] = f2tf32(bv1.z); Bs[nb][bK + 8][bCol + 3] = f2tf32(bv1.w);
            __syncthreads();
            buf = nb;
        }
    }

    // epilogue: bias + activation, float2 stores
#pragma unroll
    for (int i = 0; i < 4; i++) {
        int row = row0 + wRow + i * 16 + gID;
#pragma unroll
        for (int j = 0; j < 4; j++) {
            int col = col0 + wCol + j * 8 + tg * 2;
            if (col >= Dout) continue;
            float b0 = bias[col], b1 = bias[col + 1];
#pragma unroll
            for (int half = 0; half < 2; half++) {
                int r = row + half * 8;
                if (r >= N) continue;
                float v0 = acc[i][j][half * 2 + 0] + b0;
                float v1 = acc[i][j][half * 2 + 1] + b1;
                if (act == 1) {
                    v0 = 1.0f / (1.0f + expf(-v0));
                    v1 = 1.0f / (1.0f + expf(-v1));
                } else if (act == 2) {
                    v0 = 0.5f * v0 * (1.0f + erff(v0 * 0.70710678118654752f));
                    v1 = 0.5f * v1 * (1.0f + erff(v1 * 0.70710678118654752f));
                }
                *reinterpret_cast<float2*>(Cm + (size_t)r * Dout + col) =
                    make_float2(v0, v1);
            }
        }
    }
}

// ---------------- flow attention: one block per (b, h) ----------------
__global__ __launch_bounds__(256)
void attn_kernel(const float* __restrict__ q, const float* __restrict__ k,
                 const float* __restrict__ v, float* __restrict__ out) {
    int b = blockIdx.x >> 3, h = blockIdx.x & 7;
    const float* qp = q + ((size_t)b * LTOK) * DMOD + h * EH;
    const float* kp = k + ((size_t)b * LTOK) * DMOD + h * EH;
    const float* vp = v + ((size_t)b * LTOK) * DMOD + h * EH;
    float*       op = out + ((size_t)b * LTOK) * DMOD + h * EH;
    int tid = threadIdx.x, lane = tid & 31, wid = tid >> 5;
    const float eps = 1e-6f;

    __shared__ float s_nr[LTOK], s_nc[LTOK], s_nrref[LTOK], s_ncref[LTOK];
    __shared__ float s_ksum[EH], s_qsum[EH], s_kns[EH], s_qns[EH];
    __shared__ float s_kv[EH][EH];
    __shared__ float s_ck[8][EH], s_cv[8][EH];
    __shared__ float s_red[8];

    // Phase A: column sums of q, k
    {
        int e = tid & 63, part = tid >> 6;
        float ka = 0.f, qa = 0.f;
        for (int s = part; s < LTOK; s += 4) {
            ka += kp[(size_t)s * DMOD + e];
            qa += qp[(size_t)s * DMOD + e];
        }
        s_ck[part][e] = ka;
        s_cv[part][e] = qa;
    }
    __syncthreads();
    if (tid < EH) {
        s_ksum[tid] = s_ck[0][tid] + s_ck[1][tid] + s_ck[2][tid] + s_ck[3][tid];
        s_qsum[tid] = s_cv[0][tid] + s_cv[1][tid] + s_cv[2][tid] + s_cv[3][tid];
    }
    __syncthreads();

    // Phase B: nr, nc
    for (int r = wid; r < LTOK; r += 8) {
        float qv0 = qp[(size_t)r * DMOD + lane], qv1 = qp[(size_t)r * DMOD + lane + 32];
        float kv0 = kp[(size_t)r * DMOD + lane], kv1 = kp[(size_t)r * DMOD + lane + 32];
        float dq = (qv0 + eps) * (s_ksum[lane] + eps) + (qv1 + eps) * (s_ksum[lane + 32] + eps);
        float dk = (kv0 + eps) * (s_qsum[lane] + eps) + (kv1 + eps) * (s_qsum[lane + 32] + eps);
        for (int o = 16; o; o >>= 1) {
            dq += __shfl_xor_sync(0xffffffffu, dq, o);
            dk += __shfl_xor_sync(0xffffffffu, dk, o);
        }
        if (lane == 0) { s_nr[r] = 1.0f / dq; s_nc[r] = 1.0f / dk; }
    }
    __syncthreads();

    // Phase C: weighted column sums
    {
        int e = tid & 63, part = tid >> 6;
        float ka = 0.f, qa = 0.f;
        for (int s = part; s < LTOK; s += 4) {
            ka += kp[(size_t)s * DMOD + e] * s_nc[s];
            qa += qp[(size_t)s * DMOD + e] * s_nr[s];
        }
        s_ck[part][e] = ka;
        s_cv[part][e] = qa;
    }
    __syncthreads();
    if (tid < EH) {
        s_kns[tid] = s_ck[0][tid] + s_ck[1][tid] + s_ck[2][tid] + s_ck[3][tid];
        s_qns[tid] = s_cv[0][tid] + s_cv[1][tid] + s_cv[2][tid] + s_cv[3][tid];
    }
    __syncthreads();

    // Phase D: nr_ref, nc_ref logits
    for (int r = wid; r < LTOK; r += 8) {
        float qv0 = qp[(size_t)r * DMOD + lane], qv1 = qp[(size_t)r * DMOD + lane + 32];
        float kv0 = kp[(size_t)r * DMOD + lane], kv1 = kp[(size_t)r * DMOD + lane + 32];
        float dq = (qv0 + eps) * (s_kns[lane] + eps) + (qv1 + eps) * (s_kns[lane + 32] + eps);
        float dk = (kv0 + eps) * (s_qns[lane] + eps) + (kv1 + eps) * (s_qns[lane + 32] + eps);
        for (int o = 16; o; o >>= 1) {
            dq += __shfl_xor_sync(0xffffffffu, dq, o);
            dk += __shfl_xor_sync(0xffffffffu, dk, o);
        }
        if (lane == 0) {
            s_nrref[r] = 1.0f / (1.0f + expf(-dq));
            s_ncref[r] = dk;
        }
    }
    __syncthreads();

    // Phase E: softmax * Ls
    float lmax = -1e30f;
    for (int s = tid; s < LTOK; s += 256) lmax = fmaxf(lmax, s_ncref[s]);
    for (int o = 16; o; o >>= 1) lmax = fmaxf(lmax, __shfl_xor_sync(0xffffffffu, lmax, o));
    if (lane == 0) s_red[wid] = lmax;
    __syncthreads();
    if (tid == 0) {
        float m = s_red[0];
        for (int i = 1; i < 8; i++) m = fmaxf(m, s_red[i]);
        s_red[0] = m;
    }
    __syncthreads();
    lmax = s_red[0];
    __syncthreads();
    float lsum = 0.f;
    for (int s = tid; s < LTOK; s += 256) {
        float ev = expf(s_ncref[s] - lmax);
        s_ncref[s] = ev;
        lsum += ev;
    }
    for (int o = 16; o; o >>= 1) lsum += __shfl_xor_sync(0xffffffffu, lsum, o);
    if (lane == 0) s_red[wid] = lsum;
    __syncthreads();
    if (tid == 0) {
        float m = 0.f;
        for (int i = 0; i < 8; i++) m += s_red[i];
        s_red[0] = m;
    }
    __syncthreads();
    float scl = (float)LTOK / s_red[0];
    __syncthreads();
    for (int s = tid; s < LTOK; s += 256) s_ncref[s] *= scl;
    __syncthreads();

    // Phase F: kv[e][d]
    int e_own = tid >> 2;
    int d0    = (tid & 3) * 16;
    float acc[16];
#pragma unroll
    for (int i = 0; i < 16; i++) acc[i] = 0.f;
    for (int s0 = 0; s0 < LTOK; s0 += 8) {
        for (int i = tid; i < 512; i += 256) {
            int j = i >> 6, e = i & 63;
            int s = s0 + j;
            float kk = 0.f, vv = 0.f;
            if (s < LTOK) {
                kk = kp[(size_t)s * DMOD + e];
                vv = vp[(size_t)s * DMOD + e] * s_ncref[s];
            }
            s_ck[j][e] = kk;
            s_cv[j][e] = vv;
        }
        __syncthreads();
#pragma unroll
        for (int j = 0; j < 8; j++) {
            float ke = s_ck[j][e_own];
#pragma unroll
            for (int i = 0; i < 16; i++) acc[i] += ke * s_cv[j][d0 + i];
        }
        __syncthreads();
    }
#pragma unroll
    for (int i = 0; i < 16; i++) s_kv[e_own][d0 + i] = acc[i];
    __syncthreads();

    // Phase G: output
    for (int r = wid; r < LTOK; r += 8) {
        s_ck[wid][lane]      = qp[(size_t)r * DMOD + lane];
        s_ck[wid][lane + 32] = qp[(size_t)r * DMOD + lane + 32];
        __syncwarp();
        float a0 = 0.f, a1 = 0.f;
#pragma unroll
        for (int e = 0; e < EH; e++) {
            float qv = s_ck[wid][e];
            a0 += qv * s_kv[e][lane];
            a1 += qv * s_kv[e][lane + 32];
        }
        float sc = s_nr[r] * s_nrref[r];
        op[(size_t)r * DMOD + lane]      = a0 * sc;
        op[(size_t)r * DMOD + lane + 32] = a1 * sc;
        __syncwarp();
    }
}

// ---------------- residual add + LayerNorm ----------------
__global__ __launch_bounds__(256)
void add_ln_kernel(float* __restrict__ x, const float* __restrict__ res,
                   const float* __restrict__ w, const float* __restrict__ bb,
                   int useRes) {
    __shared__ float s_s[8], s_q[8];
    int row = blockIdx.x, tid = threadIdx.x, lane = tid & 31, wid = tid >> 5;
    size_t base = (size_t)row * DMOD;
    float v0 = x[base + tid], v1 = x[base + tid + 256];
    if (useRes) { v0 += res[base + tid]; v1 += res[base + tid + 256]; }
    float s = v0 + v1, q = v0 * v0 + v1 * v1;
    for (int o = 16; o; o >>= 1) {
        s += __shfl_xor_sync(0xffffffffu, s, o);
        q += __shfl_xor_sync(0xffffffffu, q, o);
    }
    if (lane == 0) { s_s[wid] = s; s_q[wid] = q; }
    __syncthreads();
    if (tid == 0) {
        float ss = 0.f, qq = 0.f;
        for (int i = 0; i < 8; i++) { ss += s_s[i]; qq += s_q[i]; }
        s_s[0] = ss; s_q[0] = qq;
    }
    __syncthreads();
    float mu  = s_s[0] * (1.0f / DMOD);
    float var = s_q[0] * (1.0f / DMOD) - mu * mu;
    float r   = rsqrtf(var + 1e-5f);
    x[base + tid]       = (v0 - mu) * r * w[tid] + bb[tid];
    x[base + tid + 256] = (v1 - mu) * r * w[tid + 256] + bb[tid + 256];
}

// ---------------- output: transpose + RevIN denorm ----------------
__global__ void out_kernel(const float* __restrict__ proj,
                           const float* __restrict__ rw, const float* __restrict__ rb,
                           const float* __restrict__ mean, const float* __restrict__ stdv,
                           float* __restrict__ out) {
    int idx = blockIdx.x * blockDim.x + threadIdx.x;
    const int total = BB * PRED * CC;
    if (idx >= total) return;
    int c = idx % CC;
    int t = (idx / CC) % PRED;
    int b = idx / (CC * PRED);
    float p = proj[((size_t)b * LTOK + c) * PRED + t];
    float v = (p - rb[c]) / (rw[c] + 1e-10f);
    out[idx] = v * stdv[b * CC + c] + mean[b * CC + c];
}

// ---------------- host orchestration ----------------
static inline void launch_gemm(const float* A, const float* W, const float* bias,
                               float* Cm, int N, int K, int Dout, int act) {
    dim3 grid((Dout + 127) / 128, (N + 127) / 128);
    gemm_tf32_kernel<<<grid, 256>>>(A, W, bias, Cm, N, K, Dout, act);
}

extern "C" void kernel_launch(void* const* d_in, const int* in_sizes, int n_in,
                              void* d_out, int out_size) {
    const float* x_enc   = (const float*)d_in[0];
    const float* x_mark  = (const float*)d_in[1];
    const float* revin_w = (const float*)d_in[4];
    const float* revin_b = (const float*)d_in[5];
    const float* emb_W   = (const float*)d_in[6];
    const float* emb_b   = (const float*)d_in[7];
    const float* Wq = (const float*)d_in[8],  *bq = (const float*)d_in[9];
    const float* Wk = (const float*)d_in[10], *bk = (const float*)d_in[11];
    const float* Wv = (const float*)d_in[12], *bv = (const float*)d_in[13];
    const float* Wo = (const float*)d_in[14], *bo = (const float*)d_in[15];
    const float* ff1_W = (const float*)d_in[16], *ff1_b = (const float*)d_in[17];
    const float* ff2_W = (const float*)d_in[18], *ff2_b = (const float*)d_in[19];
    const float* ln1_w = (const float*)d_in[20], *ln1_b = (const float*)d_in[21];
    const float* ln2_w = (const float*)d_in[22], *ln2_b = (const float*)d_in[23];
    const float* lnf_w = (const float*)d_in[24], *lnf_b = (const float*)d_in[25];
    const float* proj_W = (const float*)d_in[26], *proj_b = (const float*)d_in[27];

    float *tok, *x, *q, *k, *v, *a, *tmp, *ff, *proj, *mean, *stdv, *rstd;
    cudaGetSymbolAddress((void**)&tok,  g_tok);
    cudaGetSymbolAddress((void**)&x,    g_x);
    cudaGetSymbolAddress((void**)&q,    g_q);
    cudaGetSymbolAddress((void**)&k,    g_k);
    cudaGetSymbolAddress((void**)&v,    g_v);
    cudaGetSymbolAddress((void**)&a,    g_a);
    cudaGetSymbolAddress((void**)&tmp,  g_tmp);
    cudaGetSymbolAddress((void**)&ff,   g_ff);
    cudaGetSymbolAddress((void**)&proj, g_proj);
    cudaGetSymbolAddress((void**)&mean, g_mean);
    cudaGetSymbolAddress((void**)&stdv, g_std);
    cudaGetSymbolAddress((void**)&rstd, g_rstd);

    revin_stats_kernel<<<dim3((CC + 127) / 128, BB), 128>>>(x_enc, mean, stdv, rstd);
    {
        int total = BB * LTOK * TT;
        build_tok_kernel<<<(total + 255) / 256, 256>>>(x_enc, x_mark, mean, rstd,
                                                       revin_w, revin_b, tok);
    }
    launch_gemm(tok, emb_W, emb_b, x, NROW, TT, DMOD, 0);

    for (int l = 0; l < LAYERS; l++) {
        const float* wq = Wq + (size_t)l * DMOD * DMOD;
        const float* wk = Wk + (size_t)l * DMOD * DMOD;
        const float* wv = Wv + (size_t)l * DMOD * DMOD;
        const float* wo = Wo + (size_t)l * DMOD * DMOD;
        launch_gemm(x, wq, bq + l * DMOD, q, NROW, DMOD, DMOD, 1);
        launch_gemm(x, wk, bk + l * DMOD, k, NROW, DMOD, DMOD, 1);
        launch_gemm(x, wv, bv + l * DMOD, v, NROW, DMOD, DMOD, 0);
        attn_kernel<<<BB * HH, 256>>>(q, k, v, a);
        launch_gemm(a, wo, bo + l * DMOD, tmp, NROW, DMOD, DMOD, 0);
        add_ln_kernel<<<NROW, 256>>>(x, tmp, ln1_w + l * DMOD, ln1_b + l * DMOD, 1);
        launch_gemm(x, ff1_W + (size_t)l * DMOD * FFD, ff1_b + l * FFD, ff,
                    NROW, DMOD, FFD, 2);
        launch_gemm(ff, ff2_W + (size_t)l * FFD * DMOD, ff2_b + l * DMOD, tmp,
                    NROW, FFD, DMOD, 0);
        add_ln_kernel<<<NROW, 256>>>(x, tmp, ln2_w + l * DMOD, ln2_b + l * DMOD, 1);
    }
    add_ln_kernel<<<NROW, 256>>>(x, nullptr, lnf_w, lnf_b, 0);
    launch_gemm(x, proj_W, proj_b, proj, NROW, DMOD, PRED, 0);
    {
        int total = BB * PRED * CC;
        out_kernel<<<(total + 255) / 256, 256>>>(proj, revin_w, revin_b, mean, stdv,
                                                 (float*)d_out);
    }
}